// round 4
// baseline (speedup 1.0000x reference)
#include <cuda_runtime.h>
#include <cuda_fp16.h>

// Problem constants
#define HD   160
#define PLN  25600          // W*D
#define VOL  4096000        // H*W*D
#define NVOX 8192000ULL     // 2*160^3
#define WT   40             // w outputs per passA block
#define ROWS 50             // WT + 2*5
#define SPF  172            // padded smem row floats (6 + 160 + 6), even
#define HSEG 40             // h-segment in passB
#define NBB  1280           // passB grid size: 4*160*2

// Normalized 1D Gaussian, KS=11, sigma=1.5
__device__ constexpr float GW[11] = {
    0.00102838f, 0.00759876f, 0.03600077f, 0.10936070f, 0.21300553f,
    0.26601172f,
    0.21300553f, 0.10936070f, 0.03600077f, 0.00759876f, 0.00102838f
};

constexpr float C1f  = 1.0e-4f;
constexpr float C2f  = 9.0e-4f;
constexpr float EPSf = 1.0e-12f;

// fp16 scratch: 5 blurred fields, each NVOX elements.
__device__ __half gh_buf[5ULL * NVOX];
__device__ double g_acc;            // zero-initialized at load; reset by last block
__device__ unsigned int g_ticket;

__device__ __forceinline__ int refl(int i) {
    return (i < 0) ? -i : ((i > HD - 1) ? (2 * (HD - 1) - i) : i);
}

// ---------------------------------------------------------------------------
// Pass A: block = (w-tile of 40, one h, one b). 80 threads; thread t owns the
// d-pair (2t, 2t+1). Smem holds 50 w-rows of s and r, padded+reflected along d.
// D-blur: per element compute s^2, r^2, s*r once, accumulate with FFMA-imm
// into a 10-float accumulator (5 fields x 2 voxels). 11-row register ring,
// W-blur emitted from registers (all FFMA-imm), stored as __half2.
// ---------------------------------------------------------------------------
__global__ void __launch_bounds__(80) passA(const float* __restrict__ src,
                                            const float* __restrict__ ref) {
    extern __shared__ float sm[];
    float* S = sm;                   // [ROWS][SPF]
    float* R = sm + ROWS * SPF;

    const int t  = threadIdx.x;
    const int b  = blockIdx.z;
    const int h  = blockIdx.y;
    const int w0 = blockIdx.x * WT;

    const size_t basebh = ((size_t)(b * HD + h)) * PLN;

    // Load ROWS w-lines, reflect in w and in d (physical j -> global j-6).
    {
        const int ga = refl(t - 6);
        const int gb = refl(t + 74);
        const int gc = refl(t + 154);
        for (int row = 0; row < ROWS; ++row) {
            int w = w0 - 5 + row;
            w = (w < 0) ? -w : ((w > 159) ? 318 - w : w);
            const float* ps = src + basebh + (size_t)w * HD;
            const float* pr = ref + basebh + (size_t)w * HD;
            S[row * SPF + t]       = __ldg(ps + ga);
            R[row * SPF + t]       = __ldg(pr + ga);
            S[row * SPF + t + 80]  = __ldg(ps + gb);
            R[row * SPF + t + 80]  = __ldg(pr + gb);
            if (t < 12) {
                S[row * SPF + t + 160] = __ldg(ps + gc);
                R[row * SPF + t + 160] = __ldg(pr + gc);
            }
        }
    }
    __syncthreads();

    // Register ring: 5 fields x 11 rows x 2 voxels.
    float2 q0[11], q1[11], q2[11], q3[11], q4[11];

    #pragma unroll
    for (int r = 0; r < ROWS; ++r) {
        const float2* Srow = reinterpret_cast<const float2*>(S + r * SPF) + t;
        const float2* Rrow = reinterpret_cast<const float2*>(R + r * SPF) + t;

        float b0x = 0.f, b0y = 0.f, b1x = 0.f, b1y = 0.f, b2x = 0.f,
              b2y = 0.f, b3x = 0.f, b3y = 0.f, b4x = 0.f, b4y = 0.f;

        #pragma unroll
        for (int p = 0; p < 7; ++p) {
            const float2 sv = Srow[p];
            const float2 rv = Rrow[p];
            #pragma unroll
            for (int c = 0; c < 2; ++c) {
                const int k0 = 2 * p + c - 1;   // tap for voxel x (d=2t)
                const int k1 = 2 * p + c - 2;   // tap for voxel y (d=2t+1)
                const bool u0 = (k0 >= 0) && (k0 <= 10);
                const bool u1 = (k1 >= 0) && (k1 <= 10);
                if (u0 || u1) {
                    const float s  = c ? sv.y : sv.x;
                    const float v  = c ? rv.y : rv.x;
                    const float ss = s * s;
                    const float vv = v * v;
                    const float svp = s * v;
                    if (u0) {
                        b0x = fmaf(GW[k0], s,   b0x);
                        b1x = fmaf(GW[k0], v,   b1x);
                        b2x = fmaf(GW[k0], ss,  b2x);
                        b3x = fmaf(GW[k0], vv,  b3x);
                        b4x = fmaf(GW[k0], svp, b4x);
                    }
                    if (u1) {
                        b0y = fmaf(GW[k1], s,   b0y);
                        b1y = fmaf(GW[k1], v,   b1y);
                        b2y = fmaf(GW[k1], ss,  b2y);
                        b3y = fmaf(GW[k1], vv,  b3y);
                        b4y = fmaf(GW[k1], svp, b4y);
                    }
                }
            }
        }

        const int sl = r % 11;
        q0[sl] = make_float2(b0x, b0y);
        q1[sl] = make_float2(b1x, b1y);
        q2[sl] = make_float2(b2x, b2y);
        q3[sl] = make_float2(b3x, b3y);
        q4[sl] = make_float2(b4x, b4y);

        if (r >= 10) {
            float m0x = 0.f, m0y = 0.f, m1x = 0.f, m1y = 0.f, m2x = 0.f,
                  m2y = 0.f, m3x = 0.f, m3y = 0.f, m4x = 0.f, m4y = 0.f;
            #pragma unroll
            for (int k = 0; k < 11; ++k) {
                const int s2 = (r - 10 + k) % 11;
                m0x = fmaf(GW[k], q0[s2].x, m0x); m0y = fmaf(GW[k], q0[s2].y, m0y);
                m1x = fmaf(GW[k], q1[s2].x, m1x); m1y = fmaf(GW[k], q1[s2].y, m1y);
                m2x = fmaf(GW[k], q2[s2].x, m2x); m2y = fmaf(GW[k], q2[s2].y, m2y);
                m3x = fmaf(GW[k], q3[s2].x, m3x); m3y = fmaf(GW[k], q3[s2].y, m3y);
                m4x = fmaf(GW[k], q4[s2].x, m4x); m4y = fmaf(GW[k], q4[s2].y, m4y);
            }
            const size_t off = basebh + (size_t)(w0 + r - 10) * HD + 2 * t;
            *reinterpret_cast<__half2*>(gh_buf + 0ULL * NVOX + off) = __floats2half2_rn(m0x, m0y);
            *reinterpret_cast<__half2*>(gh_buf + 1ULL * NVOX + off) = __floats2half2_rn(m1x, m1y);
            *reinterpret_cast<__half2*>(gh_buf + 2ULL * NVOX + off) = __floats2half2_rn(m2x, m2y);
            *reinterpret_cast<__half2*>(gh_buf + 3ULL * NVOX + off) = __floats2half2_rn(m3x, m3y);
            *reinterpret_cast<__half2*>(gh_buf + 4ULL * NVOX + off) = __floats2half2_rn(m4x, m4y);
        }
    }
}

// ---------------------------------------------------------------------------
// Pass B: H-blur on fp16 scratch via 11-plane register ring (half2 loads,
// 2 voxels/thread), SSIM, block reduce, global atomic + ticket finalize.
// 80 threads; grid (HD/HSEG, W, B) = 1280 blocks.
// ---------------------------------------------------------------------------
__global__ void __launch_bounds__(80) passB(float* __restrict__ out) {
    const int t  = threadIdx.x;
    const int b  = blockIdx.z;
    const int w  = blockIdx.y;
    const int h0 = blockIdx.x * HSEG;

    const size_t colbase = (size_t)b * VOL + (size_t)w * HD + 2 * t;

    float2 win[5][11];

    #pragma unroll
    for (int j = 0; j < 10; ++j) {
        const int q = refl(h0 - 5 + j);
        const size_t off = colbase + (size_t)q * PLN;
        #pragma unroll
        for (int f = 0; f < 5; ++f)
            win[f][j] = __half22float2(
                *reinterpret_cast<const __half2*>(gh_buf + (size_t)f * NVOX + off));
    }

    float acc = 0.f;

    #pragma unroll
    for (int i = 0; i < HSEG; ++i) {
        {
            const int q = refl(h0 + i + 5);
            const size_t off = colbase + (size_t)q * PLN;
            const int slot = (i + 10) % 11;
            #pragma unroll
            for (int f = 0; f < 5; ++f)
                win[f][slot] = __half22float2(
                    *reinterpret_cast<const __half2*>(gh_buf + (size_t)f * NVOX + off));
        }
        float mu1x = 0.f, mu1y = 0.f, mu2x = 0.f, mu2y = 0.f, m11x = 0.f,
              m11y = 0.f, m22x = 0.f, m22y = 0.f, m12x = 0.f, m12y = 0.f;
        #pragma unroll
        for (int k = 0; k < 11; ++k) {
            const int sl = (i + k) % 11;
            mu1x = fmaf(GW[k], win[0][sl].x, mu1x); mu1y = fmaf(GW[k], win[0][sl].y, mu1y);
            mu2x = fmaf(GW[k], win[1][sl].x, mu2x); mu2y = fmaf(GW[k], win[1][sl].y, mu2y);
            m11x = fmaf(GW[k], win[2][sl].x, m11x); m11y = fmaf(GW[k], win[2][sl].y, m11y);
            m22x = fmaf(GW[k], win[3][sl].x, m22x); m22y = fmaf(GW[k], win[3][sl].y, m22y);
            m12x = fmaf(GW[k], win[4][sl].x, m12x); m12y = fmaf(GW[k], win[4][sl].y, m12y);
        }
        {
            const float a = mu1x * mu1x, bb = mu2x * mu2x, c = mu1x * mu2x;
            const float s1 = m11x - a, s2 = m22x - bb, s12 = m12x - c;
            const float num = (2.f * c + C1f) * (2.f * s12 + C2f);
            const float den = (a + bb + C1f) * (s1 + s2 + C2f);
            acc += __fdividef(num, den + EPSf);
        }
        {
            const float a = mu1y * mu1y, bb = mu2y * mu2y, c = mu1y * mu2y;
            const float s1 = m11y - a, s2 = m22y - bb, s12 = m12y - c;
            const float num = (2.f * c + C1f) * (2.f * s12 + C2f);
            const float den = (a + bb + C1f) * (s1 + s2 + C2f);
            acc += __fdividef(num, den + EPSf);
        }
    }

    // Block tree reduce (80 threads), then global atomic + ticket finalize.
    __shared__ float red[80];
    red[t] = acc;
    __syncthreads();
    if (t < 40) red[t] += red[t + 40];
    __syncthreads();
    if (t < 20) red[t] += red[t + 20];
    __syncthreads();
    if (t < 10) red[t] += red[t + 10];
    __syncthreads();
    if (t < 5)  red[t] += red[t + 5];
    __syncthreads();

    if (t == 0) {
        const float s = red[0] + red[1] + red[2] + red[3] + red[4];
        atomicAdd(&g_acc, (double)s);
        __threadfence();
        const unsigned done = atomicAdd(&g_ticket, 1u);
        if (done == NBB - 1) {
            const double v = atomicAdd(&g_acc, 0.0);   // coherent read
            out[0] = (float)(1.0 - v / (double)NVOX);
            g_acc = 0.0;
            g_ticket = 0u;
            __threadfence();
        }
    }
}

extern "C" void kernel_launch(void* const* d_in, const int* in_sizes, int n_in,
                              void* d_out, int out_size) {
    const float* src = (const float*)d_in[0];
    const float* ref = (const float*)d_in[1];
    float* out = (float*)d_out;

    const int smemA = 2 * ROWS * SPF * (int)sizeof(float);   // 68800 B
    cudaFuncSetAttribute(passA, cudaFuncAttributeMaxDynamicSharedMemorySize, smemA);

    passA<<<dim3(HD / WT, HD, 2), 80, smemA>>>(src, ref);
    passB<<<dim3(HD / HSEG, HD, 2), 80>>>(out);
}